// round 3
// baseline (speedup 1.0000x reference)
#include <cuda_runtime.h>
#include <cstdint>

#define TT  12
#define NN  50000
#define EE  800000
#define TN  (TT*NN)          /* 600000 */
#define FIN 128
#define HH  64

// ------------------------- static device scratch -------------------------
__device__ float d_xw[(size_t)TN*64];          // xs @ W_gcn
__device__ float d_cur[(size_t)TN*64];         // GCN output
__device__ float d_gicur[(size_t)TN*192];      // cur @ W_ih[:, :64]^T
__device__ float d_yring[(size_t)3*NN*192];    // h_t @ W_s^T ring
__device__ float d_gring[3*NN];                // attention scalar ring
__device__ float d_dinv[TN];
__device__ int   d_cnt[TN];
__device__ int   d_fill[TN];
__device__ int   d_rowptr[TN];
__device__ int   d_ebuf[(size_t)TT*EE];
__device__ float d_WcT[64*192];                // [k][j] = W_ih[j][k]
__device__ float d_Wcat[64*256];               // [k][j]=W_ih[j][64+k]; [k][192+i]=Q[i][k]
__device__ int   d_bsum[1024];

// ------------------------- helpers -------------------------
__device__ __forceinline__ void ffma2(unsigned long long& d,
                                      unsigned long long a,
                                      unsigned long long b)
{
    asm("fma.rn.f32x2 %0, %1, %2, %0;" : "+l"(d) : "l"(a), "l"(b));
}

__device__ __forceinline__ float2 u2f2(unsigned long long u)
{
    float2 f;
    asm("mov.b64 {%0,%1}, %2;" : "=f"(f.x), "=f"(f.y) : "l"(u));
    return f;
}

// ------------------------- weight prep -------------------------
__global__ void k_prep(const float* __restrict__ W_ih, const float* __restrict__ Q,
                       float* __restrict__ WcT, float* __restrict__ Wcat)
{
    for (int i = threadIdx.x; i < 64*192; i += 256) {
        int k = i / 192, j = i % 192;
        WcT[(size_t)k*192 + j]  = W_ih[(size_t)j*128 + k];
        Wcat[(size_t)k*256 + j] = W_ih[(size_t)j*128 + 64 + k];
    }
    for (int i = threadIdx.x; i < 64*64; i += 256) {
        int k = i / 64, q = i % 64;
        Wcat[(size_t)k*256 + 192 + q] = Q[(size_t)q*64 + k];
    }
}

__global__ void k_zero(int* __restrict__ a, int n)
{
    int i = blockIdx.x*256 + threadIdx.x;
    if (i < n) a[i] = 0;
}

// ------------------------- CSR build -------------------------
__global__ void k_count(const int* __restrict__ ei, int* __restrict__ cnt)
{
    int e = blockIdx.x*256 + threadIdx.x;
    int t = blockIdx.y;
    if (e < EE) {
        int dst = ei[(size_t)t*2*EE + EE + e];
        atomicAdd(&cnt[t*NN + dst], 1);
    }
}

__global__ void k_scan1(const int* __restrict__ cnt, int* __restrict__ incl,
                        int* __restrict__ bsum, int n)
{
    __shared__ int ws[32];
    int tid  = threadIdx.x;
    int i    = blockIdx.x*1024 + tid;
    int lane = tid & 31, wid = tid >> 5;
    int v = (i < n) ? cnt[i] : 0;
    int x = v;
#pragma unroll
    for (int o = 1; o < 32; o <<= 1) {
        int y = __shfl_up_sync(0xffffffffu, x, o);
        if (lane >= o) x += y;
    }
    if (lane == 31) ws[wid] = x;
    __syncthreads();
    if (wid == 0) {
        int s = ws[lane];
#pragma unroll
        for (int o = 1; o < 32; o <<= 1) {
            int y = __shfl_up_sync(0xffffffffu, s, o);
            if (lane >= o) s += y;
        }
        ws[lane] = s;
    }
    __syncthreads();
    if (wid > 0) x += ws[wid-1];
    if (i < n) incl[i] = x;
    if (tid == 1023) bsum[blockIdx.x] = x;
}

__global__ void k_scan2(int* __restrict__ bsum, int nb)
{
    __shared__ int ws[32];
    int tid  = threadIdx.x;
    int lane = tid & 31, wid = tid >> 5;
    int v = (tid < nb) ? bsum[tid] : 0;
    int x = v;
#pragma unroll
    for (int o = 1; o < 32; o <<= 1) {
        int y = __shfl_up_sync(0xffffffffu, x, o);
        if (lane >= o) x += y;
    }
    if (lane == 31) ws[wid] = x;
    __syncthreads();
    if (wid == 0) {
        int s = ws[lane];
#pragma unroll
        for (int o = 1; o < 32; o <<= 1) {
            int y = __shfl_up_sync(0xffffffffu, s, o);
            if (lane >= o) s += y;
        }
        ws[lane] = s;
    }
    __syncthreads();
    if (wid > 0) x += ws[wid-1];
    if (tid < nb) bsum[tid] = x - v;   // exclusive
}

__global__ void k_scan3(const int* __restrict__ cnt, int* __restrict__ incl_then_rowptr,
                        const int* __restrict__ bsum, int* __restrict__ fill,
                        float* __restrict__ dinv, int n)
{
    int i = blockIdx.x*1024 + threadIdx.x;
    if (i < n) {
        int c  = cnt[i];
        int ex = incl_then_rowptr[i] - c + bsum[blockIdx.x];
        incl_then_rowptr[i] = ex;
        fill[i] = ex;
        dinv[i] = rsqrtf(1.0f + (float)c);
    }
}

__global__ void k_fill(const int* __restrict__ ei, int* __restrict__ fill,
                       int* __restrict__ ebuf)
{
    int e = blockIdx.x*256 + threadIdx.x;
    int t = blockIdx.y;
    if (e < EE) {
        int src = ei[(size_t)t*2*EE + e];
        int dst = ei[(size_t)t*2*EE + EE + e];
        int pos = atomicAdd(&fill[t*NN + dst], 1);
        ebuf[pos] = t*NN + src;
    }
}

// ------------------------- gather (GCN aggregation) -------------------------
__global__ void k_gather(const float* __restrict__ xw, const float* __restrict__ bg,
                         float* __restrict__ cur,
                         const int* __restrict__ rowptr, const int* __restrict__ cnt,
                         const float* __restrict__ dinv, const int* __restrict__ ebuf)
{
    int w    = blockIdx.x*8 + (threadIdx.x >> 5);
    int lane = threadIdx.x & 31;
    if (w >= TN) return;
    int start = rowptr[w];
    int c     = cnt[w];
    float a0 = 0.f, a1 = 0.f;
    for (int b0 = 0; b0 < c; b0 += 32) {
        int rem  = c - b0;
        int mcnt = rem < 32 ? rem : 32;
        int idx  = (lane < mcnt) ? ebuf[start + b0 + lane] : 0;
        float dv = (lane < mcnt) ? dinv[idx] : 0.f;
#pragma unroll 4
        for (int e = 0; e < mcnt; e++) {
            int   g  = __shfl_sync(0xffffffffu, idx, e);
            float wv = __shfl_sync(0xffffffffu, dv,  e);
            a0 += wv * xw[(size_t)g*64 + lane];
            a1 += wv * xw[(size_t)g*64 + 32 + lane];
        }
    }
    float ds = dinv[w];
    float s0 = xw[(size_t)w*64 + lane];
    float s1 = xw[(size_t)w*64 + 32 + lane];
    cur[(size_t)w*64 + lane]      = ds*(a0 + ds*s0) + bg[lane];
    cur[(size_t)w*64 + 32 + lane] = ds*(a1 + ds*s1) + bg[32 + lane];
}

// ------------------------- tiled GEMM (f32x2), C = A[M,K] @ B[K,ldb] tile -------------------------
#define BM 128
#define BN 64
#define BK 16
__global__ void k_gemm(const float* __restrict__ A, const float* __restrict__ B,
                       float* __restrict__ C, int M, int K, int ldb)
{
    __shared__ __align__(16) float ATd[BK][2*BM + 8];   // A transposed + duplicated, stride 264
    __shared__ __align__(16) float Bs[BK][BN];
    int tid  = threadIdx.x;
    int row0 = blockIdx.x * BM;
    int nb   = blockIdx.y * BN;
    int r0   = (tid >> 4) * 8;     // 8 rows per thread
    int c0   = (tid & 15) * 4;     // 4 cols per thread
    unsigned long long acc[8][2];
#pragma unroll
    for (int r = 0; r < 8; r++) { acc[r][0] = 0ull; acc[r][1] = 0ull; }

    for (int kk = 0; kk < K; kk += BK) {
        // load+transpose+duplicate A tile (128 x 16)
#pragma unroll
        for (int q = 0; q < 2; q++) {
            int f  = tid*2 + q;
            int r  = f >> 2;
            int kq = (f & 3) * 4;
            int grow = row0 + r;
            float4 v = make_float4(0.f, 0.f, 0.f, 0.f);
            if (grow < M) v = *(const float4*)&A[(size_t)grow*K + kk + kq];
            *(float2*)&ATd[kq+0][2*r] = make_float2(v.x, v.x);
            *(float2*)&ATd[kq+1][2*r] = make_float2(v.y, v.y);
            *(float2*)&ATd[kq+2][2*r] = make_float2(v.z, v.z);
            *(float2*)&ATd[kq+3][2*r] = make_float2(v.w, v.w);
        }
        // load B tile (16 x 64)
        {
            int kb = tid >> 4;
            int cf = (tid & 15) * 4;
            *(float4*)&Bs[kb][cf] = *(const float4*)&B[(size_t)(kk + kb)*ldb + nb + cf];
        }
        __syncthreads();
#pragma unroll
        for (int k = 0; k < BK; k++) {
            ulonglong2 a0 = *(const ulonglong2*)&ATd[k][2*r0];
            ulonglong2 a1 = *(const ulonglong2*)&ATd[k][2*r0 + 4];
            ulonglong2 a2 = *(const ulonglong2*)&ATd[k][2*r0 + 8];
            ulonglong2 a3 = *(const ulonglong2*)&ATd[k][2*r0 + 12];
            ulonglong2 b  = *(const ulonglong2*)&Bs[k][c0];
            ffma2(acc[0][0], a0.x, b.x); ffma2(acc[0][1], a0.x, b.y);
            ffma2(acc[1][0], a0.y, b.x); ffma2(acc[1][1], a0.y, b.y);
            ffma2(acc[2][0], a1.x, b.x); ffma2(acc[2][1], a1.x, b.y);
            ffma2(acc[3][0], a1.y, b.x); ffma2(acc[3][1], a1.y, b.y);
            ffma2(acc[4][0], a2.x, b.x); ffma2(acc[4][1], a2.x, b.y);
            ffma2(acc[5][0], a2.y, b.x); ffma2(acc[5][1], a2.y, b.y);
            ffma2(acc[6][0], a3.x, b.x); ffma2(acc[6][1], a3.x, b.y);
            ffma2(acc[7][0], a3.y, b.x); ffma2(acc[7][1], a3.y, b.y);
        }
        __syncthreads();
    }
#pragma unroll
    for (int r = 0; r < 8; r++) {
        int grow = row0 + r0 + r;
        if (grow < M) {
            float2 lo = u2f2(acc[r][0]);
            float2 hi = u2f2(acc[r][1]);
            *(float4*)&C[(size_t)grow*ldb + nb + c0] = make_float4(lo.x, lo.y, hi.x, hi.y);
        }
    }
}

// ------------------------- fused step: attention + GRU + y/g GEMM -------------------------
__global__ void k_step(int t,
                       const float* __restrict__ gi_cur_t,
                       float* __restrict__ yring, float* __restrict__ gring,
                       const float* __restrict__ Wcat, const float* __restrict__ r_vec,
                       const float* __restrict__ b_ih, const float* __restrict__ b_hh,
                       float* __restrict__ out_t)
{
    __shared__ __align__(16) float hd[64][68];   // h duplicated: hd[k][2*ni], 32 nodes/chunk
    int tid  = threadIdx.x;
    int base = blockIdx.x * 32;
    int slot = t % 3;

    // ---------------- Phase A: attention weights + GRU -> h ----------------
    {
        int j = tid & 63;
        float bi0 = b_ih[j], bi1 = b_ih[64+j], bi2 = b_ih[128+j];
        float bh0 = b_hh[j], bh1 = b_hh[64+j], bh2 = b_hh[128+j];
        for (int ni = tid >> 6; ni < 32; ni += 4) {
            int n = base + ni;
            if (n < NN) {
                float e[3], a[3];
                float mx = -1e30f;
#pragma unroll
                for (int p = 0; p < 3; p++) {
                    int  idx = t - 3 + p;
                    bool val = (p >= 2 - t);
                    e[p] = val ? ((idx >= 0) ? gring[(idx % 3)*NN + n] : 0.0f) : -1e30f;
                    mx = fmaxf(mx, e[p]);
                }
                float s = 0.f;
#pragma unroll
                for (int p = 0; p < 3; p++) {
                    a[p] = (e[p] > -1e29f) ? __expf(e[p] - mx) : 0.0f;
                    s += a[p];
                }
                float inv = 1.0f / s;
                float g0 = gi_cur_t[(size_t)n*192 + j]       + bi0;
                float g1 = gi_cur_t[(size_t)n*192 + 64 + j]  + bi1;
                float g2 = gi_cur_t[(size_t)n*192 + 128 + j] + bi2;
#pragma unroll
                for (int p = 0; p < 3; p++) {
                    int idx = t - 3 + p;
                    if (idx >= 0) {
                        float wgt = a[p] * inv;
                        const float* y = &yring[(size_t)(idx % 3)*NN*192 + (size_t)n*192];
                        g0 += wgt * y[j];
                        g1 += wgt * y[64 + j];
                        g2 += wgt * y[128 + j];
                    }
                }
                float rr  = 1.0f / (1.0f + __expf(-(g0 + bh0)));
                float zz  = 1.0f / (1.0f + __expf(-(g1 + bh1)));
                float nnv = tanhf(g2 + rr * bh2);
                float h   = (1.0f - zz) * nnv;
                out_t[(size_t)n*64 + j] = h;
                hd[j][2*ni]   = h;
                hd[j][2*ni+1] = h;
            } else {
                hd[j][2*ni]   = 0.f;
                hd[j][2*ni+1] = 0.f;
            }
        }
    }
    __syncthreads();

    // ---------------- Phase B: y = h @ Wcat  (cols 0..191 -> yring, 192..255 -> scores g) ----------------
    {
        int cg = tid & 31;          // 8 columns per thread
        int nq = tid >> 5;          // 4 nodes per thread
        int c0 = cg * 8;
        unsigned long long acc[4][4];
#pragma unroll
        for (int m = 0; m < 4; m++)
#pragma unroll
            for (int q = 0; q < 4; q++) acc[m][q] = 0ull;

#pragma unroll 8
        for (int k = 0; k < 64; k++) {
            ulonglong2 ha = *(const ulonglong2*)&hd[k][8*nq];
            ulonglong2 hb = *(const ulonglong2*)&hd[k][8*nq + 4];
            ulonglong2 wa = *(const ulonglong2*)&Wcat[(size_t)k*256 + c0];
            ulonglong2 wb = *(const ulonglong2*)&Wcat[(size_t)k*256 + c0 + 4];
            ffma2(acc[0][0], ha.x, wa.x); ffma2(acc[0][1], ha.x, wa.y);
            ffma2(acc[0][2], ha.x, wb.x); ffma2(acc[0][3], ha.x, wb.y);
            ffma2(acc[1][0], ha.y, wa.x); ffma2(acc[1][1], ha.y, wa.y);
            ffma2(acc[1][2], ha.y, wb.x); ffma2(acc[1][3], ha.y, wb.y);
            ffma2(acc[2][0], hb.x, wa.x); ffma2(acc[2][1], hb.x, wa.y);
            ffma2(acc[2][2], hb.x, wb.x); ffma2(acc[2][3], hb.x, wb.y);
            ffma2(acc[3][0], hb.y, wa.x); ffma2(acc[3][1], hb.y, wa.y);
            ffma2(acc[3][2], hb.y, wb.x); ffma2(acc[3][3], hb.y, wb.y);
        }

        if (c0 < 192) {
#pragma unroll
            for (int m = 0; m < 4; m++) {
                int n = base + nq*4 + m;
                if (n < NN) {
                    float2 p0 = u2f2(acc[m][0]);
                    float2 p1 = u2f2(acc[m][1]);
                    float2 p2 = u2f2(acc[m][2]);
                    float2 p3 = u2f2(acc[m][3]);
                    float* y = &yring[(size_t)slot*NN*192 + (size_t)n*192 + c0];
                    *(float4*)&y[0] = make_float4(p0.x, p0.y, p1.x, p1.y);
                    *(float4*)&y[4] = make_float4(p2.x, p2.y, p3.x, p3.y);
                }
            }
        } else {
            int zc = c0 - 192;      // 0..56
            float rv[8];
#pragma unroll
            for (int i = 0; i < 8; i++) rv[i] = r_vec[zc + i];
#pragma unroll
            for (int m = 0; m < 4; m++) {
                float2 p0 = u2f2(acc[m][0]);
                float2 p1 = u2f2(acc[m][1]);
                float2 p2 = u2f2(acc[m][2]);
                float2 p3 = u2f2(acc[m][3]);
                float part = rv[0]*tanhf(p0.x) + rv[1]*tanhf(p0.y)
                           + rv[2]*tanhf(p1.x) + rv[3]*tanhf(p1.y)
                           + rv[4]*tanhf(p2.x) + rv[5]*tanhf(p2.y)
                           + rv[6]*tanhf(p3.x) + rv[7]*tanhf(p3.y);
                part += __shfl_down_sync(0xFF000000u, part, 4);
                part += __shfl_down_sync(0xFF000000u, part, 2);
                part += __shfl_down_sync(0xFF000000u, part, 1);
                if (cg == 24) {
                    int n = base + nq*4 + m;
                    if (n < NN) gring[slot*NN + n] = part;
                }
            }
        }
    }
}

// ------------------------- launcher -------------------------
extern "C" void kernel_launch(void* const* d_in, const int* in_sizes, int n_in,
                              void* d_out, int out_size)
{
    const float* xs    = (const float*)d_in[0];
    const int*   ei    = (const int*)  d_in[1];
    const float* W_gcn = (const float*)d_in[2];
    const float* b_gcn = (const float*)d_in[3];
    const float* Q     = (const float*)d_in[4];
    const float* r_vec = (const float*)d_in[5];
    const float* W_ih  = (const float*)d_in[6];
    const float* b_ih  = (const float*)d_in[8];
    const float* b_hh  = (const float*)d_in[9];
    float* out = (float*)d_out;

    float *p_xw, *p_cur, *p_gic, *p_yr, *p_gr, *p_dinv, *p_WcT, *p_Wcat;
    int   *p_cnt, *p_fill, *p_rp, *p_eb, *p_bs;
    cudaGetSymbolAddress((void**)&p_xw,   d_xw);
    cudaGetSymbolAddress((void**)&p_cur,  d_cur);
    cudaGetSymbolAddress((void**)&p_gic,  d_gicur);
    cudaGetSymbolAddress((void**)&p_yr,   d_yring);
    cudaGetSymbolAddress((void**)&p_gr,   d_gring);
    cudaGetSymbolAddress((void**)&p_dinv, d_dinv);
    cudaGetSymbolAddress((void**)&p_WcT,  d_WcT);
    cudaGetSymbolAddress((void**)&p_Wcat, d_Wcat);
    cudaGetSymbolAddress((void**)&p_cnt,  d_cnt);
    cudaGetSymbolAddress((void**)&p_fill, d_fill);
    cudaGetSymbolAddress((void**)&p_rp,   d_rowptr);
    cudaGetSymbolAddress((void**)&p_eb,   d_ebuf);
    cudaGetSymbolAddress((void**)&p_bs,   d_bsum);

    const int nsb = (TN + 1023) / 1024;   // 586 scan blocks

    k_prep <<<1, 256>>>(W_ih, Q, p_WcT, p_Wcat);
    k_zero <<<(TN + 255)/256, 256>>>(p_cnt, TN);
    k_count<<<dim3((EE + 255)/256, TT), 256>>>(ei, p_cnt);

    // xw = xs @ W_gcn   [600000,128]x[128,64]
    k_gemm <<<dim3((TN + BM - 1)/BM, 1), 256>>>(xs, W_gcn, p_xw, TN, FIN, HH);

    k_scan1<<<nsb, 1024>>>(p_cnt, p_rp, p_bs, TN);
    k_scan2<<<1, 1024>>>(p_bs, nsb);
    k_scan3<<<nsb, 1024>>>(p_cnt, p_rp, p_bs, p_fill, p_dinv, TN);
    k_fill <<<dim3((EE + 255)/256, TT), 256>>>(ei, p_fill, p_eb);

    k_gather<<<(TN + 7)/8, 256>>>(p_xw, b_gcn, p_cur, p_rp, p_cnt, p_dinv, p_eb);

    // gi_cur = cur @ W_c^T   [600000,64]x[64,192]
    k_gemm <<<dim3((TN + BM - 1)/BM, 3), 256>>>(p_cur, p_WcT, p_gic, TN, HH, 192);

    for (int t = 0; t < TT; t++) {
        k_step<<<(NN + 31)/32, 256>>>(t,
                                      p_gic + (size_t)t*NN*192,
                                      p_yr, p_gr,
                                      p_Wcat, r_vec, b_ih, b_hh,
                                      out + (size_t)t*NN*64);
    }
}